// round 1
// baseline (speedup 1.0000x reference)
#include <cuda_runtime.h>
#include <math.h>

// Problem constants
#define BATCH 8
#define CIN   128
#define OCH   384      // 3 * CIN  (q,k,v)
#define HH    96
#define WW    96
#define PP    (HH*WW)  // 9216
#define NHEAD 4
#define DHEAD 32
#define RSQRT_D 0.17677669529663687f  // 1/sqrt(32)

// Scratch for qkv result t[b][o][h][w]  (113 MB, static device array: allowed)
__device__ float g_t[(size_t)BATCH * OCH * PP];

// ---------------------------------------------------------------------------
// Kernel A: QKV GEMM.  t[b, o, p] = sum_c W[o,c] * x[b, c, p]
// Tile: 128 (o) x 128 (p) x full K=128.  256 threads, 8x8 register blocking.
// Smem: Ws[c][o] padded to 129 (conflict-free transposed store), Xs[c][p].
// ---------------------------------------------------------------------------
__global__ __launch_bounds__(256) void qkv_gemm(const float* __restrict__ x,
                                                const float* __restrict__ Wt) {
    extern __shared__ float sm[];
    float* Ws = sm;              // [128][129]  Ws[c*129 + o_local]
    float* Xs = sm + 128 * 129;  // [128][128]  Xs[c*128 + p_local]

    const int tid = threadIdx.x;
    const int p0  = blockIdx.x * 128;
    const int o0  = blockIdx.y * 128;
    const int b   = blockIdx.z;
    const float* xb = x + (size_t)b * CIN * PP;

    // Load W tile [o0..o0+128) x [0..128) transposed into Ws[c][o]
    for (int i = tid; i < 128 * 128; i += 256) {
        int r = i >> 7;      // o-local
        int c = i & 127;     // cin
        Ws[c * 129 + r] = Wt[(o0 + r) * 128 + c];
    }
    // Load X tile [0..128) x [p0..p0+128)
    for (int i = tid; i < 128 * 128; i += 256) {
        int c = i >> 7;
        int p = i & 127;
        Xs[c * 128 + p] = xb[(size_t)c * PP + p0 + p];
    }
    __syncthreads();

    const int tx = tid & 15;
    const int ty = tid >> 4;

    float acc[8][8];
#pragma unroll
    for (int i = 0; i < 8; i++)
#pragma unroll
        for (int j = 0; j < 8; j++) acc[i][j] = 0.f;

#pragma unroll 2
    for (int k = 0; k < 128; k++) {
        float a[8], bb[8];
#pragma unroll
        for (int i = 0; i < 4; i++) {
            a[i]     = Ws[k * 129 + (ty << 2) + i];
            a[4 + i] = Ws[k * 129 + 64 + (ty << 2) + i];
        }
        float4 b0 = *(const float4*)&Xs[k * 128 + (tx << 2)];
        float4 b1 = *(const float4*)&Xs[k * 128 + 64 + (tx << 2)];
        bb[0] = b0.x; bb[1] = b0.y; bb[2] = b0.z; bb[3] = b0.w;
        bb[4] = b1.x; bb[5] = b1.y; bb[6] = b1.z; bb[7] = b1.w;
#pragma unroll
        for (int i = 0; i < 8; i++)
#pragma unroll
            for (int j = 0; j < 8; j++) acc[i][j] += a[i] * bb[j];
    }

    // Store 8x8 block (two float4 per row)
#pragma unroll
    for (int i = 0; i < 8; i++) {
        int ol = ((i >> 2) << 6) + (ty << 2) + (i & 3);
        float* dst = g_t + ((size_t)(b * OCH + o0 + ol)) * PP + p0;
        float4 v0 = make_float4(acc[i][0], acc[i][1], acc[i][2], acc[i][3]);
        float4 v1 = make_float4(acc[i][4], acc[i][5], acc[i][6], acc[i][7]);
        *(float4*)(dst + (tx << 2))      = v0;
        *(float4*)(dst + 64 + (tx << 2)) = v1;
    }
}

// ---------------------------------------------------------------------------
// Kernel B: 3x3 neighborhood attention.
// Grid: (36 tiles of 16x16, 4 heads, 8 batches).  One thread per position.
// Smem: qs[32][256], ks[32][18*18], vs[32][18*18] (zero-padded halo == the
// reference's zero padding: OOB neighbors get logit 0 and v 0, exactly as ref).
// ---------------------------------------------------------------------------
__global__ __launch_bounds__(256) void attn_kernel(float* __restrict__ out) {
    extern __shared__ float sm[];
    float* qs = sm;                    // [32][256]
    float* ks = sm + 32 * 256;         // [32][324]
    float* vs = ks + 32 * 324;         // [32][324]

    const int tid  = threadIdx.x;
    const int tile = blockIdx.x;
    const int ty0  = (tile / 6) * 16;
    const int tx0  = (tile % 6) * 16;
    const int g    = blockIdx.y;
    const int b    = blockIdx.z;

    const float* qb = g_t + ((size_t)(b * OCH) + g * DHEAD) * PP;
    const float* kb = g_t + ((size_t)(b * OCH) + CIN + g * DHEAD) * PP;
    const float* vb = g_t + ((size_t)(b * OCH) + 2 * CIN + g * DHEAD) * PP;

    const int tx = tid & 15;
    const int ty = tid >> 4;

    // q tile (interior only)
#pragma unroll 4
    for (int c = 0; c < DHEAD; c++)
        qs[c * 256 + tid] = qb[(size_t)c * PP + (ty0 + ty) * WW + tx0 + tx];

    // k, v halo tiles (18x18, zero-filled out of bounds)
    for (int c = 0; c < DHEAD; c++) {
        for (int i = tid; i < 324; i += 256) {
            int yy = i / 18;
            int xx = i - yy * 18;
            int gy = ty0 - 1 + yy;
            int gx = tx0 - 1 + xx;
            bool ok = (gy >= 0) && (gy < HH) && (gx >= 0) && (gx < WW);
            int gi = c * PP + gy * WW + gx;
            ks[c * 324 + i] = ok ? kb[gi] : 0.f;
            vs[c * 324 + i] = ok ? vb[gi] : 0.f;
        }
    }
    __syncthreads();

    float qreg[DHEAD];
#pragma unroll
    for (int d = 0; d < DHEAD; d++) qreg[d] = qs[d * 256 + tid];

    float att[9];
#pragma unroll
    for (int n = 0; n < 9; n++) {
        const int hp = (ty + n / 3) * 18 + tx + (n % 3);
        float s = 0.f;
#pragma unroll
        for (int d = 0; d < DHEAD; d++) s += qreg[d] * ks[d * 324 + hp];
        att[n] = s * RSQRT_D;
    }

    float m = att[0];
#pragma unroll
    for (int n = 1; n < 9; n++) m = fmaxf(m, att[n]);
    float ssum = 0.f;
#pragma unroll
    for (int n = 0; n < 9; n++) { att[n] = __expf(att[n] - m); ssum += att[n]; }
    float inv = 1.f / ssum;
#pragma unroll
    for (int n = 0; n < 9; n++) att[n] *= inv;

    float* op = out + ((size_t)(b * CIN + g * DHEAD)) * PP + (ty0 + ty) * WW + tx0 + tx;
#pragma unroll
    for (int d = 0; d < DHEAD; d++) {
        float o = 0.f;
#pragma unroll
        for (int n = 0; n < 9; n++) {
            const int hp = (ty + n / 3) * 18 + tx + (n % 3);
            o += att[n] * vs[d * 324 + hp];
        }
        op[(size_t)d * PP] = o;
    }
}

// ---------------------------------------------------------------------------
extern "C" void kernel_launch(void* const* d_in, const int* in_sizes, int n_in,
                              void* d_out, int out_size) {
    const float* x  = (const float*)d_in[0];   // [8,128,96,96]
    const float* Wt = (const float*)d_in[1];   // [384,128]
    float* out = (float*)d_out;                // [8,128,96,96]

    const int smA = (128 * 129 + 128 * 128) * sizeof(float);      // ~128.5 KB
    const int smB = (32 * 256 + 2 * 32 * 324) * sizeof(float);    // ~113 KB

    cudaFuncSetAttribute(qkv_gemm,   cudaFuncAttributeMaxDynamicSharedMemorySize, smA);
    cudaFuncSetAttribute(attn_kernel, cudaFuncAttributeMaxDynamicSharedMemorySize, smB);

    qkv_gemm<<<dim3(PP / 128, OCH / 128, BATCH), 256, smA>>>(x, Wt);
    attn_kernel<<<dim3((HH / 16) * (WW / 16), NHEAD, BATCH), 256, smB>>>(out);
}

// round 4
// speedup vs baseline: 1.3571x; 1.3571x over previous
#include <cuda_runtime.h>
#include <cstdint>
#include <math.h>

// ---------------------------------------------------------------------------
// Problem constants
// ---------------------------------------------------------------------------
#define BATCH 8
#define CIN   128
#define OCH   384
#define HH    96
#define WW    96
#define PP    (HH*WW)          // 9216
#define NHEAD 4
#define DHEAD 32
#define RSQRT_D 0.17677669529663687f

// t layout: [b][g][qkv][p][d]  (d=32 contiguous per position)
__device__ float g_t[(size_t)BATCH * OCH * PP];

// ---------------------------------------------------------------------------
// Packed f32x2 FMA (PTX sm_100+ family feature; NOT an 'a'-suffix feature)
// ---------------------------------------------------------------------------
__device__ __forceinline__ void ffma2(uint64_t& d, uint64_t a, uint64_t b) {
    asm("fma.rn.f32x2 %0, %1, %2, %0;" : "+l"(d) : "l"(a), "l"(b));
}
__device__ __forceinline__ uint64_t dup2(float v) {
    uint64_t r;
    uint32_t u = __float_as_uint(v);
    asm("mov.b64 %0, {%1, %1};" : "=l"(r) : "r"(u));
    return r;
}
union F2U { uint64_t u; float2 f; };

// ---------------------------------------------------------------------------
// Kernel A: QKV GEMM, SIMT with f32x2 packed FMAs.
//   t[p][o] = sum_c W[o,c] * x[b,c,p]
// Tile 128(o) x 128(p) x K=128, 256 threads, 8x8 per-thread tile (as 8x4 f32x2).
// Epilogue transposes through smem and writes t[b][g][qkv][p][d] coalesced.
// Grid: (72 p-tiles, 3 qkv slabs, 8 batches).
// ---------------------------------------------------------------------------
static constexpr int WS_STRIDE = 132;           // float4-aligned, low-conflict
static constexpr int GEMM_SMEM = (128 * WS_STRIDE + 128 * 128) * 4;  // 133120 B

__global__ __launch_bounds__(256) void qkv_gemm(const float* __restrict__ x,
                                                const float* __restrict__ Wt) {
    extern __shared__ float sm[];
    float* Ws = sm;                       // [128 c][132]  Ws[c*132 + o_local]
    float* Xs = sm + 128 * WS_STRIDE;     // [128 c][128]  Xs[c*128 + p_local]
    float* Cs = sm;                       // reused post-loop: [128 p][132] C^T

    const int tid = threadIdx.x;
    const int p0  = blockIdx.x * 128;
    const int ot  = blockIdx.y;           // qkv slab
    const int o0  = ot * 128;
    const int b   = blockIdx.z;
    const float* xb = x + (size_t)b * CIN * PP;

    // ---- Load W tile transposed: Ws[c][o_local] ----
    for (int i = tid; i < 4096; i += 256) {
        int r  = i >> 5;                  // o-local
        int cg = i & 31;                  // c group of 4
        float4 w = *(const float4*)&Wt[(o0 + r) * 128 + cg * 4];
        Ws[(4 * cg + 0) * WS_STRIDE + r] = w.x;
        Ws[(4 * cg + 1) * WS_STRIDE + r] = w.y;
        Ws[(4 * cg + 2) * WS_STRIDE + r] = w.z;
        Ws[(4 * cg + 3) * WS_STRIDE + r] = w.w;
    }
    // ---- Load X tile: Xs[c][p_local] ----
    for (int i = tid; i < 4096; i += 256) {
        int c  = i >> 5;
        int pg = i & 31;
        *(float4*)&Xs[c * 128 + pg * 4] =
            *(const float4*)&xb[(size_t)c * PP + p0 + pg * 4];
    }
    __syncthreads();

    const int tx = tid & 15;              // p dim
    const int ty = tid >> 4;              // o dim

    uint64_t acc2[8][4];
#pragma unroll
    for (int i = 0; i < 8; i++)
#pragma unroll
        for (int j = 0; j < 4; j++) acc2[i][j] = 0ull;

#pragma unroll 4
    for (int k = 0; k < 128; k++) {
        float4 wa0 = *(const float4*)&Ws[k * WS_STRIDE + (ty << 2)];
        float4 wa1 = *(const float4*)&Ws[k * WS_STRIDE + 64 + (ty << 2)];
        ulonglong2 xv0 = *(const ulonglong2*)&Xs[k * 128 + (tx << 2)];
        ulonglong2 xv1 = *(const ulonglong2*)&Xs[k * 128 + 64 + (tx << 2)];
        uint64_t b2[4] = {xv0.x, xv0.y, xv1.x, xv1.y};
        float a[8] = {wa0.x, wa0.y, wa0.z, wa0.w, wa1.x, wa1.y, wa1.z, wa1.w};
#pragma unroll
        for (int i = 0; i < 8; i++) {
            uint64_t a2 = dup2(a[i]);
#pragma unroll
            for (int jp = 0; jp < 4; jp++) ffma2(acc2[i][jp], a2, b2[jp]);
        }
    }

    __syncthreads();                      // done reading Ws/Xs; reuse as Cs

    // ---- Stage C^T in smem: Cs[p_local][o_local] ----
#pragma unroll
    for (int jj = 0; jj < 8; jj++) {
        const int p_l = (jj < 4) ? (tx * 4 + jj) : (64 + tx * 4 + (jj - 4));
        const int jp  = (jj < 4) ? (jj >> 1) : (2 + ((jj - 4) >> 1));
        const int h   = jj & 1;
        float v[8];
#pragma unroll
        for (int i = 0; i < 8; i++) {
            F2U u; u.u = acc2[i][jp];
            v[i] = h ? u.f.y : u.f.x;
        }
        *(float4*)&Cs[p_l * WS_STRIDE + (ty << 2)] =
            make_float4(v[0], v[1], v[2], v[3]);
        *(float4*)&Cs[p_l * WS_STRIDE + 64 + (ty << 2)] =
            make_float4(v[4], v[5], v[6], v[7]);
    }
    __syncthreads();

    // ---- Coalesced global store: t[b][g][ot][p][d] ----
    for (int i = tid; i < 4096; i += 256) {
        int p_l = i >> 5;
        int f   = i & 31;                 // float4 index within 128 channels
        int g   = f >> 3;
        int d4  = f & 7;
        float4 v = *(const float4*)&Cs[p_l * WS_STRIDE + f * 4];
        float* dst = g_t + (((size_t)(b * 4 + g) * 3 + ot) * PP + p0 + p_l) * 32 + d4 * 4;
        *(float4*)dst = v;
    }
}

// ---------------------------------------------------------------------------
// Kernel B: 3x3 neighborhood attention on [p][d] layout.
// CTA = 16x16 tile, 256 threads (1 pos/thread). One 18x18x32 halo buffer,
// used for K then reused for V. q in registers. 46.7 KB smem -> 4 CTAs/SM.
// Zero-filled OOB halo == reference's zero padding (logit 0, v 0).
// ---------------------------------------------------------------------------
static constexpr int HALO = 324;           // 18*18
static constexpr int HPAD = 36;            // floats per halo position
static constexpr int ATT_SMEM = HALO * HPAD * 4;   // 46656 B

__device__ __forceinline__ void load_halo(float* sm, const float* __restrict__ src,
                                          int ty0, int tx0, int tid) {
    for (int i = tid; i < HALO * 8; i += 256) {
        int pos = i >> 3, f4 = i & 7;
        int yy = pos / 18;
        int xx = pos - yy * 18;
        int gy = ty0 - 1 + yy;
        int gx = tx0 - 1 + xx;
        float4 v = make_float4(0.f, 0.f, 0.f, 0.f);
        if (gy >= 0 && gy < HH && gx >= 0 && gx < WW)
            v = *reinterpret_cast<const float4*>(src + ((size_t)(gy * WW + gx)) * 32 + f4 * 4);
        *reinterpret_cast<float4*>(sm + pos * HPAD + f4 * 4) = v;
    }
}

__global__ __launch_bounds__(256) void attn_kernel(float* __restrict__ out) {
    extern __shared__ float sm[];
    const int tid  = threadIdx.x;
    const int tile = blockIdx.x;
    const int ty0  = (tile / 6) * 16;
    const int tx0  = (tile % 6) * 16;
    const int g    = blockIdx.y;
    const int b    = blockIdx.z;
    const int tx = tid & 15;
    const int ty = tid >> 4;

    const size_t hb = (size_t)(b * 4 + g) * 3;
    const float* qb = g_t + (hb + 0) * PP * 32;
    const float* kb = g_t + (hb + 1) * PP * 32;
    const float* vb = g_t + (hb + 2) * PP * 32;

    // K halo
    load_halo(sm, kb, ty0, tx0, tid);

    // q into registers (contiguous 128 B per thread)
    const float* qp = qb + ((size_t)((ty0 + ty) * WW + tx0 + tx)) * 32;
    float4 q4[8];
#pragma unroll
    for (int j = 0; j < 8; j++) q4[j] = *reinterpret_cast<const float4*>(qp + 4 * j);

    int hp9[9];
#pragma unroll
    for (int n = 0; n < 9; n++) hp9[n] = (ty + n / 3) * 18 + tx + (n % 3);

    __syncthreads();

    float att[9];
#pragma unroll
    for (int n = 0; n < 9; n++) {
        const float* kp = sm + hp9[n] * HPAD;
        float s = 0.f;
#pragma unroll
        for (int j = 0; j < 8; j++) {
            float4 kv = *reinterpret_cast<const float4*>(kp + 4 * j);
            s += q4[j].x * kv.x + q4[j].y * kv.y + q4[j].z * kv.z + q4[j].w * kv.w;
        }
        att[n] = s * RSQRT_D;
    }

    float m = att[0];
#pragma unroll
    for (int n = 1; n < 9; n++) m = fmaxf(m, att[n]);
    float ssum = 0.f;
#pragma unroll
    for (int n = 0; n < 9; n++) { att[n] = __expf(att[n] - m); ssum += att[n]; }
    float inv = 1.f / ssum;
#pragma unroll
    for (int n = 0; n < 9; n++) att[n] *= inv;

    __syncthreads();                 // everyone done reading K
    load_halo(sm, vb, ty0, tx0, tid);
    __syncthreads();

    float* op = out + ((size_t)(b * CIN + g * DHEAD)) * PP + (ty0 + ty) * WW + tx0 + tx;
#pragma unroll
    for (int j = 0; j < 8; j++) {
        float4 acc = make_float4(0.f, 0.f, 0.f, 0.f);
#pragma unroll
        for (int n = 0; n < 9; n++) {
            float4 vv = *reinterpret_cast<const float4*>(sm + hp9[n] * HPAD + 4 * j);
            acc.x += att[n] * vv.x; acc.y += att[n] * vv.y;
            acc.z += att[n] * vv.z; acc.w += att[n] * vv.w;
        }
        op[(size_t)(4 * j + 0) * PP] = acc.x;
        op[(size_t)(4 * j + 1) * PP] = acc.y;
        op[(size_t)(4 * j + 2) * PP] = acc.z;
        op[(size_t)(4 * j + 3) * PP] = acc.w;
    }
}

// ---------------------------------------------------------------------------
extern "C" void kernel_launch(void* const* d_in, const int* in_sizes, int n_in,
                              void* d_out, int out_size) {
    const float* x  = (const float*)d_in[0];   // [8,128,96,96]
    const float* Wt = (const float*)d_in[1];   // [384,128]
    float* out = (float*)d_out;                // [8,128,96,96]

    cudaFuncSetAttribute(qkv_gemm,   cudaFuncAttributeMaxDynamicSharedMemorySize, GEMM_SMEM);
    cudaFuncSetAttribute(attn_kernel, cudaFuncAttributeMaxDynamicSharedMemorySize, ATT_SMEM);

    qkv_gemm<<<dim3(PP / 128, 3, BATCH), 256, GEMM_SMEM>>>(x, Wt);
    attn_kernel<<<dim3((HH / 16) * (WW / 16), NHEAD, BATCH), 256, ATT_SMEM>>>(out);
}

// round 7
// speedup vs baseline: 2.9708x; 2.1891x over previous
#include <cuda_runtime.h>
#include <cuda_bf16.h>
#include <cstdint>
#include <math.h>

// ---------------------------------------------------------------------------
// Problem constants
// ---------------------------------------------------------------------------
#define BATCH 8
#define CIN   128
#define HH    96
#define WW    96
#define PP    (HH*WW)          // 9216
#define RSQRT_D 0.17677669529663687f

// t layout: [b][g][qkv][p][d]  (d=32 contiguous per position)
__device__ float g_t[(size_t)BATCH * 384 * PP];

// ---------------------------------------------------------------------------
// GEMM smem layout: bf16 tiles, row stride 136 elems (272 B) -> conflict-free
// ldmatrix (row byte-offsets step 16 mod 128).
// ---------------------------------------------------------------------------
static constexpr int TS   = 136;        // bf16 elems per row
static constexpr int TSB  = TS * 2;     // 272 bytes
static constexpr int XHI  = 0;
static constexpr int XLO  = 128 * TSB;          // 34816
static constexpr int WHI  = 2 * 128 * TSB;      // 69632
static constexpr int WLO  = 3 * 128 * TSB;      // 104448
static constexpr int GEMM_SMEM = 4 * 128 * TSB; // 139264 B

__device__ __forceinline__ uint32_t smem_u32(const void* p) {
    uint32_t a;
    asm("{ .reg .u64 t; cvta.to.shared.u64 t, %1; cvt.u32.u64 %0, t; }" : "=r"(a) : "l"(p));
    return a;
}
__device__ __forceinline__ void ldm_x4(uint32_t r[4], uint32_t a) {
    asm volatile("ldmatrix.sync.aligned.m8n8.x4.shared.b16 {%0,%1,%2,%3}, [%4];"
                 : "=r"(r[0]), "=r"(r[1]), "=r"(r[2]), "=r"(r[3]) : "r"(a));
}
__device__ __forceinline__ void mma16816(float* c, const uint32_t* a, const uint32_t* b) {
    asm volatile("mma.sync.aligned.m16n8k16.row.col.f32.bf16.bf16.f32 "
                 "{%0,%1,%2,%3}, {%4,%5,%6,%7}, {%8,%9}, {%0,%1,%2,%3};"
                 : "+f"(c[0]), "+f"(c[1]), "+f"(c[2]), "+f"(c[3])
                 : "r"(a[0]), "r"(a[1]), "r"(a[2]), "r"(a[3]), "r"(b[0]), "r"(b[1]));
}
// split two fp32 into packed bf16x2 hi + lo (lo = residual)
__device__ __forceinline__ void split2(float f0, float f1, uint32_t& hi, uint32_t& lo) {
    __nv_bfloat16 h0 = __float2bfloat16(f0);
    __nv_bfloat16 h1 = __float2bfloat16(f1);
    __nv_bfloat16 l0 = __float2bfloat16(f0 - __bfloat162float(h0));
    __nv_bfloat16 l1 = __float2bfloat16(f1 - __bfloat162float(h1));
    hi = ((uint32_t)*reinterpret_cast<uint16_t*>(&h1) << 16) | *reinterpret_cast<uint16_t*>(&h0);
    lo = ((uint32_t)*reinterpret_cast<uint16_t*>(&l1) << 16) | *reinterpret_cast<uint16_t*>(&l0);
}

// ---------------------------------------------------------------------------
// Kernel A: QKV GEMM via mma.sync bf16 (3-term hi/lo split, fp32 accum).
//   t[p][o] = sum_c X[c][p] * W[o][c]
// CTA: 128 p x 128 o, K=128. X^T staged once; loop over 3 qkv W slabs.
// 8 warps = 2(p) x 4(o); warp tile 64 x 32 = 4 m-frags x 4 n-frags.
// Grid: (72 p-tiles, 8 batches).
// ---------------------------------------------------------------------------
__global__ __launch_bounds__(256) void qkv_mma(const float* __restrict__ x,
                                               const float* __restrict__ Wt) {
    extern __shared__ char smc[];
    const uint32_t smb = smem_u32(smc);
    const int tid = threadIdx.x;
    const int p0  = blockIdx.x * 128;
    const int b   = blockIdx.y;

    // ---- Stage X^T (hi/lo): thread handles half a p-row (64 channels) ----
    {
        const int row  = tid & 127;
        const int half = tid >> 7;
        const float* xp = x + (size_t)b * CIN * PP + p0 + row;
        uint32_t* xh = reinterpret_cast<uint32_t*>(smc + XHI + row * TSB + half * 128);
        uint32_t* xl = reinterpret_cast<uint32_t*>(smc + XLO + row * TSB + half * 128);
#pragma unroll
        for (int j = 0; j < 32; j++) {
            int c = half * 64 + 2 * j;
            float f0 = xp[(size_t)c * PP];
            float f1 = xp[(size_t)(c + 1) * PP];
            uint32_t hi, lo;
            split2(f0, f1, hi, lo);
            xh[j] = hi;
            xl[j] = lo;
        }
    }

    const int lane = tid & 31, wid = tid >> 5;
    const int wp = wid & 1;          // p: 2 x 64
    const int wo = wid >> 1;         // o: 4 x 32  (== head g within slab)
    const int sel = lane >> 3, idx = lane & 7;
    const int gid = lane >> 2, tig = lane & 3;

    // ldmatrix per-lane byte offsets
    const uint32_t aoff = (uint32_t)((idx + (sel & 1) * 8) * TSB + (sel >> 1) * 16);
    const uint32_t boff = (uint32_t)((idx + (sel >> 1) * 8) * TSB + (sel & 1) * 16);
    const uint32_t aHi = smb + XHI + wp * 64 * TSB + aoff;
    const uint32_t aLo = smb + XLO + wp * 64 * TSB + aoff;
    const uint32_t bHi = smb + WHI + wo * 32 * TSB + boff;
    const uint32_t bLo = smb + WLO + wo * 32 * TSB + boff;

    for (int ot = 0; ot < 3; ot++) {
        __syncthreads();             // X staged (ot=0) / all warps done with Ws
        // ---- Stage W slab [128 o][128 c] hi/lo  (FULL 128 channels) ----
        for (int i = tid; i < 4096; i += 256) {
            int row = i >> 5, cq = i & 31;
            float4 w = *reinterpret_cast<const float4*>(&Wt[(ot * 128 + row) * 128 + cq * 4]);
            uint32_t h0, l0, h1, l1;
            split2(w.x, w.y, h0, l0);
            split2(w.z, w.w, h1, l1);
            uint32_t* wh = reinterpret_cast<uint32_t*>(smc + WHI + row * TSB + cq * 8);
            uint32_t* wl = reinterpret_cast<uint32_t*>(smc + WLO + row * TSB + cq * 8);
            wh[0] = h0; wh[1] = h1;
            wl[0] = l0; wl[1] = l1;
        }
        __syncthreads();

        float C[4][4][4];
#pragma unroll
        for (int mf = 0; mf < 4; mf++)
#pragma unroll
            for (int nf = 0; nf < 4; nf++)
#pragma unroll
                for (int r = 0; r < 4; r++) C[mf][nf][r] = 0.f;

#pragma unroll
        for (int ks = 0; ks < 8; ks++) {
            const uint32_t ko = ks * 32;
            uint32_t Ah[4][4], Al[4][4], Bh[2][4], Bl[2][4];
#pragma unroll
            for (int mf = 0; mf < 4; mf++) {
                ldm_x4(Ah[mf], aHi + mf * 16 * TSB + ko);
                ldm_x4(Al[mf], aLo + mf * 16 * TSB + ko);
            }
#pragma unroll
            for (int np = 0; np < 2; np++) {
                ldm_x4(Bh[np], bHi + np * 16 * TSB + ko);
                ldm_x4(Bl[np], bLo + np * 16 * TSB + ko);
            }
#pragma unroll
            for (int mf = 0; mf < 4; mf++) {
#pragma unroll
                for (int nf = 0; nf < 4; nf++) {
                    const uint32_t* bh = &Bh[nf >> 1][(nf & 1) * 2];
                    const uint32_t* bl = &Bl[nf >> 1][(nf & 1) * 2];
                    mma16816(C[mf][nf], Ah[mf], bh);   // hh
                    mma16816(C[mf][nf], Ah[mf], bl);   // hl
                    mma16816(C[mf][nf], Al[mf], bh);   // lh
                }
            }
        }

        // ---- Epilogue: t[b][g=wo][ot][p][d], d-contiguous float2 stores ----
#pragma unroll
        for (int mf = 0; mf < 4; mf++) {
#pragma unroll
            for (int nf = 0; nf < 4; nf++) {
                const int p_l = wp * 64 + mf * 16 + gid;
                const int d   = nf * 8 + tig * 2;
                float* dst = g_t + (((size_t)(b * 4 + wo) * 3 + ot) * PP + p0 + p_l) * 32 + d;
                *reinterpret_cast<float2*>(dst) = make_float2(C[mf][nf][0], C[mf][nf][1]);
                *reinterpret_cast<float2*>(dst + 8 * 32) = make_float2(C[mf][nf][2], C[mf][nf][3]);
            }
        }
    }
}

// ---------------------------------------------------------------------------
// Kernel B: 3x3 neighborhood attention on [p][d] layout.
// CTA = 16x16 tile, 256 threads (1 pos/thread). One 18x18x32 halo buffer,
// used for K then reused for V. q in registers. 46.7 KB smem.
// launch_bounds(256,4): cap regs at 64 -> 4 CTAs/SM.
// ---------------------------------------------------------------------------
static constexpr int HALO = 324;           // 18*18
static constexpr int HPAD = 36;
static constexpr int ATT_SMEM = HALO * HPAD * 4;   // 46656 B

__device__ __forceinline__ void load_halo(float* smf, const float* __restrict__ src,
                                          int ty0, int tx0, int tid) {
    for (int i = tid; i < HALO * 8; i += 256) {
        int pos = i >> 3, f4 = i & 7;
        int yy = pos / 18;
        int xx = pos - yy * 18;
        int gy = ty0 - 1 + yy;
        int gx = tx0 - 1 + xx;
        float4 v = make_float4(0.f, 0.f, 0.f, 0.f);
        if (gy >= 0 && gy < HH && gx >= 0 && gx < WW)
            v = *reinterpret_cast<const float4*>(src + ((size_t)(gy * WW + gx)) * 32 + f4 * 4);
        *reinterpret_cast<float4*>(smf + pos * HPAD + f4 * 4) = v;
    }
}

__global__ __launch_bounds__(256, 4) void attn_kernel(float* __restrict__ out) {
    extern __shared__ char smc[];
    float* smf = reinterpret_cast<float*>(smc);
    const int tid  = threadIdx.x;
    const int tile = blockIdx.x;
    const int ty0  = (tile / 6) * 16;
    const int tx0  = (tile % 6) * 16;
    const int g    = blockIdx.y;
    const int b    = blockIdx.z;
    const int tx = tid & 15;
    const int ty = tid >> 4;

    const size_t hb = (size_t)(b * 4 + g) * 3;
    const float* qb = g_t + (hb + 0) * PP * 32;
    const float* kb = g_t + (hb + 1) * PP * 32;
    const float* vb = g_t + (hb + 2) * PP * 32;

    load_halo(smf, kb, ty0, tx0, tid);

    const float* qp = qb + ((size_t)((ty0 + ty) * WW + tx0 + tx)) * 32;
    float4 q4[8];
#pragma unroll
    for (int j = 0; j < 8; j++) q4[j] = *reinterpret_cast<const float4*>(qp + 4 * j);

    int hp9[9];
#pragma unroll
    for (int n = 0; n < 9; n++) hp9[n] = (ty + n / 3) * 18 + tx + (n % 3);

    __syncthreads();

    float att[9];
#pragma unroll
    for (int n = 0; n < 9; n++) {
        const float* kp = smf + hp9[n] * HPAD;
        float s = 0.f;
#pragma unroll
        for (int j = 0; j < 8; j++) {
            float4 kv = *reinterpret_cast<const float4*>(kp + 4 * j);
            s += q4[j].x * kv.x + q4[j].y * kv.y + q4[j].z * kv.z + q4[j].w * kv.w;
        }
        att[n] = s * RSQRT_D;
    }

    float m = att[0];
#pragma unroll
    for (int n = 1; n < 9; n++) m = fmaxf(m, att[n]);
    float ssum = 0.f;
#pragma unroll
    for (int n = 0; n < 9; n++) { att[n] = __expf(att[n] - m); ssum += att[n]; }
    float inv = 1.f / ssum;
#pragma unroll
    for (int n = 0; n < 9; n++) att[n] *= inv;

    __syncthreads();                 // everyone done reading K
    load_halo(smf, vb, ty0, tx0, tid);
    __syncthreads();

    float* op = out + ((size_t)(b * CIN + g * 32)) * PP + (ty0 + ty) * WW + tx0 + tx;
#pragma unroll
    for (int j = 0; j < 8; j++) {
        float4 acc = make_float4(0.f, 0.f, 0.f, 0.f);
#pragma unroll
        for (int n = 0; n < 9; n++) {
            float4 vv = *reinterpret_cast<const float4*>(smf + hp9[n] * HPAD + 4 * j);
            acc.x += att[n] * vv.x; acc.y += att[n] * vv.y;
            acc.z += att[n] * vv.z; acc.w += att[n] * vv.w;
        }
        op[(size_t)(4 * j + 0) * PP] = acc.x;
        op[(size_t)(4 * j + 1) * PP] = acc.y;
        op[(size_t)(4 * j + 2) * PP] = acc.z;
        op[(size_t)(4 * j + 3) * PP] = acc.w;
    }
}

// ---------------------------------------------------------------------------
extern "C" void kernel_launch(void* const* d_in, const int* in_sizes, int n_in,
                              void* d_out, int out_size) {
    const float* x  = (const float*)d_in[0];   // [8,128,96,96]
    const float* Wt = (const float*)d_in[1];   // [384,128]
    float* out = (float*)d_out;                // [8,128,96,96]

    cudaFuncSetAttribute(qkv_mma,    cudaFuncAttributeMaxDynamicSharedMemorySize, GEMM_SMEM);
    cudaFuncSetAttribute(attn_kernel, cudaFuncAttributeMaxDynamicSharedMemorySize, ATT_SMEM);

    qkv_mma<<<dim3(PP / 128, BATCH), 256, GEMM_SMEM>>>(x, Wt);
    attn_kernel<<<dim3((HH / 16) * (WW / 16), 4, BATCH), 256, ATT_SMEM>>>(out);
}

// round 8
// speedup vs baseline: 3.4323x; 1.1553x over previous
#include <cuda_runtime.h>
#include <cuda_bf16.h>
#include <cstdint>
#include <math.h>

// ---------------------------------------------------------------------------
// Problem constants
// ---------------------------------------------------------------------------
#define BATCH 8
#define CIN   128
#define HH    96
#define WW    96
#define PP    (HH*WW)          // 9216
#define RSQRT_D 0.17677669529663687f

// t layout: [b][g][qkv][p][d]  (d=32 contiguous per position)
__device__ float g_t[(size_t)BATCH * 384 * PP];

// Pre-split W in smem-image layout: [slab(6)][hi/lo(2)][64 rows x 136 bf16]
// slab = o/64 ; row = o%64 ; 136 bf16 per row = 272 B (ldmatrix-friendly stride)
__device__ __nv_bfloat16 g_wslab[6][2][64 * 136];

// ---------------------------------------------------------------------------
// GEMM smem layout
// ---------------------------------------------------------------------------
static constexpr int TS   = 136;        // bf16 elems per row
static constexpr int TSB  = TS * 2;     // 272 bytes
static constexpr int XHI  = 0;                  // 128 rows -> 34816 B
static constexpr int XLO  = 128 * TSB;          // 34816
static constexpr int WB0  = 2 * 128 * TSB;      // 69632   (W buf 0: hi 17408 | lo 17408)
static constexpr int WB1  = WB0 + 64 * TSB * 2; // 104448  (W buf 1)
static constexpr int WLO_OFF = 64 * TSB;        // 17408 within a W buffer
static constexpr int WSLAB_BYTES = 2 * 64 * TSB;  // 34816
static constexpr int GEMM_SMEM = WB1 + WSLAB_BYTES; // 139264 B

__device__ __forceinline__ uint32_t smem_u32(const void* p) {
    uint32_t a;
    asm("{ .reg .u64 t; cvta.to.shared.u64 t, %1; cvt.u32.u64 %0, t; }" : "=r"(a) : "l"(p));
    return a;
}
__device__ __forceinline__ void ldm_x4(uint32_t r[4], uint32_t a) {
    asm volatile("ldmatrix.sync.aligned.m8n8.x4.shared.b16 {%0,%1,%2,%3}, [%4];"
                 : "=r"(r[0]), "=r"(r[1]), "=r"(r[2]), "=r"(r[3]) : "r"(a));
}
__device__ __forceinline__ void mma16816(float* c, const uint32_t* a, const uint32_t* b) {
    asm volatile("mma.sync.aligned.m16n8k16.row.col.f32.bf16.bf16.f32 "
                 "{%0,%1,%2,%3}, {%4,%5,%6,%7}, {%8,%9}, {%0,%1,%2,%3};"
                 : "+f"(c[0]), "+f"(c[1]), "+f"(c[2]), "+f"(c[3])
                 : "r"(a[0]), "r"(a[1]), "r"(a[2]), "r"(a[3]), "r"(b[0]), "r"(b[1]));
}
__device__ __forceinline__ void cp16(uint32_t dst, const void* src) {
    asm volatile("cp.async.ca.shared.global [%0], [%1], 16;" :: "r"(dst), "l"(src));
}
__device__ __forceinline__ void cp_commit() {
    asm volatile("cp.async.commit_group;" ::: "memory");
}
__device__ __forceinline__ void cp_wait1() {
    asm volatile("cp.async.wait_group 1;" ::: "memory");
}
__device__ __forceinline__ void cp_wait0() {
    asm volatile("cp.async.wait_group 0;" ::: "memory");
}
// split two fp32 into packed bf16x2 hi + lo (lo = residual)
__device__ __forceinline__ void split2(float f0, float f1, uint32_t& hi, uint32_t& lo) {
    __nv_bfloat16 h0 = __float2bfloat16(f0);
    __nv_bfloat16 h1 = __float2bfloat16(f1);
    __nv_bfloat16 l0 = __float2bfloat16(f0 - __bfloat162float(h0));
    __nv_bfloat16 l1 = __float2bfloat16(f1 - __bfloat162float(h1));
    hi = ((uint32_t)*reinterpret_cast<uint16_t*>(&h1) << 16) | *reinterpret_cast<uint16_t*>(&h0);
    lo = ((uint32_t)*reinterpret_cast<uint16_t*>(&l1) << 16) | *reinterpret_cast<uint16_t*>(&l0);
}

// ---------------------------------------------------------------------------
// Kernel 0: pre-split W into smem-image layout (runs once per launch, ~10 us)
// ---------------------------------------------------------------------------
__global__ void wprep_kernel(const float* __restrict__ Wt) {
    int i = blockIdx.x * 256 + threadIdx.x;      // over 384*64 channel-pairs
    if (i < 384 * 64) {
        int o = i >> 6, cp = i & 63;
        float2 w = *reinterpret_cast<const float2*>(&Wt[o * 128 + 2 * cp]);
        uint32_t hi, lo;
        split2(w.x, w.y, hi, lo);
        int slab = o >> 6, row = o & 63;
        reinterpret_cast<uint32_t*>(g_wslab[slab][0])[row * 68 + cp] = hi;
        reinterpret_cast<uint32_t*>(g_wslab[slab][1])[row * 68 + cp] = lo;
    }
}

// ---------------------------------------------------------------------------
// Kernel A: QKV GEMM via mma.sync bf16 (3-term hi/lo split, fp32 accum).
//   t[p][o] = sum_c X[c][p] * W[o][c]
// CTA: 128 p, K=128; loops over 6 sub-slabs of 64 o, W staged via cp.async
// double-buffer (overlapped with mma). 8 warps = 4(p) x 2(o); warp tile
// 32p x 32o = 2 mf x 4 nf. Grid: (72 p-tiles, 8 batches).
// ---------------------------------------------------------------------------
__global__ __launch_bounds__(256) void qkv_mma(const float* __restrict__ x) {
    extern __shared__ char smc[];
    const uint32_t smb = smem_u32(smc);
    const int tid = threadIdx.x;
    const int p0  = blockIdx.x * 128;
    const int b   = blockIdx.y;

    // ---- Prologue: issue cp.async for W slab 0 into buf 0 ----
    {
        const char* src = reinterpret_cast<const char*>(g_wslab[0]);
        for (int i = tid; i < WSLAB_BYTES / 16; i += 256)
            cp16(smb + WB0 + i * 16, src + i * 16);
        cp_commit();
    }

    // ---- Stage X^T (hi/lo): thread handles half a p-row (64 channels) ----
    {
        const int row  = tid & 127;
        const int half = tid >> 7;
        const float* xp = x + (size_t)b * CIN * PP + p0 + row;
        uint32_t* xh = reinterpret_cast<uint32_t*>(smc + XHI + row * TSB + half * 128);
        uint32_t* xl = reinterpret_cast<uint32_t*>(smc + XLO + row * TSB + half * 128);
#pragma unroll
        for (int j = 0; j < 32; j++) {
            int c = half * 64 + 2 * j;
            float f0 = xp[(size_t)c * PP];
            float f1 = xp[(size_t)(c + 1) * PP];
            uint32_t hi, lo;
            split2(f0, f1, hi, lo);
            xh[j] = hi;
            xl[j] = lo;
        }
    }

    const int lane = tid & 31, wid = tid >> 5;
    const int wp = wid & 3;          // p: 4 x 32
    const int wo = wid >> 2;         // o: 2 x 32
    const int sel = lane >> 3, idx = lane & 7;
    const int gid = lane >> 2, tig = lane & 3;

    // ldmatrix per-lane byte offsets
    const uint32_t aoff = (uint32_t)((idx + (sel & 1) * 8) * TSB + (sel >> 1) * 16);
    const uint32_t boff = (uint32_t)((idx + (sel >> 1) * 8) * TSB + (sel & 1) * 16);
    const uint32_t aHi = smb + XHI + wp * 32 * TSB + aoff;
    const uint32_t aLo = smb + XLO + wp * 32 * TSB + aoff;
    const uint32_t wbase = wo * 32 * TSB + boff;

    for (int s = 0; s < 6; s++) {
        const uint32_t wbuf = (s & 1) ? WB1 : WB0;
        // Issue next slab into the other buffer, then wait for current slab
        if (s < 5) {
            const uint32_t nbuf = (s & 1) ? WB0 : WB1;
            const char* src = reinterpret_cast<const char*>(g_wslab[s + 1]);
            for (int i = tid; i < WSLAB_BYTES / 16; i += 256)
                cp16(smb + nbuf + i * 16, src + i * 16);
            cp_commit();
            cp_wait1();
        } else {
            cp_wait0();
        }
        __syncthreads();

        const uint32_t bHi = smb + wbuf + wbase;
        const uint32_t bLo = bHi + WLO_OFF;

        float C[2][4][4];
#pragma unroll
        for (int mf = 0; mf < 2; mf++)
#pragma unroll
            for (int nf = 0; nf < 4; nf++)
#pragma unroll
                for (int r = 0; r < 4; r++) C[mf][nf][r] = 0.f;

#pragma unroll
        for (int ks = 0; ks < 8; ks++) {
            const uint32_t ko = ks * 32;
            uint32_t Ah[2][4], Al[2][4], Bh[2][4], Bl[2][4];
#pragma unroll
            for (int mf = 0; mf < 2; mf++) {
                ldm_x4(Ah[mf], aHi + mf * 16 * TSB + ko);
                ldm_x4(Al[mf], aLo + mf * 16 * TSB + ko);
            }
#pragma unroll
            for (int np = 0; np < 2; np++) {
                ldm_x4(Bh[np], bHi + np * 16 * TSB + ko);
                ldm_x4(Bl[np], bLo + np * 16 * TSB + ko);
            }
#pragma unroll
            for (int mf = 0; mf < 2; mf++) {
#pragma unroll
                for (int nf = 0; nf < 4; nf++) {
                    const uint32_t* bh = &Bh[nf >> 1][(nf & 1) * 2];
                    const uint32_t* bl = &Bl[nf >> 1][(nf & 1) * 2];
                    mma16816(C[mf][nf], Ah[mf], bh);   // hh
                    mma16816(C[mf][nf], Ah[mf], bl);   // hl
                    mma16816(C[mf][nf], Al[mf], bh);   // lh
                }
            }
        }

        // ---- Epilogue: t[b][g][ot][p][d], d-contiguous float2 stores ----
        const int ot = s >> 1;
#pragma unroll
        for (int mf = 0; mf < 2; mf++) {
#pragma unroll
            for (int nf = 0; nf < 4; nf++) {
                const int p_l = wp * 32 + mf * 16 + gid;
                const int oo  = (s & 1) * 64 + wo * 32 + nf * 8 + tig * 2;
                const int g   = oo >> 5;
                const int d   = oo & 31;
                float* dst = g_t + (((size_t)(b * 4 + g) * 3 + ot) * PP + p0 + p_l) * 32 + d;
                *reinterpret_cast<float2*>(dst) = make_float2(C[mf][nf][0], C[mf][nf][1]);
                *reinterpret_cast<float2*>(dst + 8 * 32) = make_float2(C[mf][nf][2], C[mf][nf][3]);
            }
        }
        __syncthreads();   // all warps done reading wbuf before it is refilled
    }
}

// ---------------------------------------------------------------------------
// Kernel B: 3x3 neighborhood attention on [p][d] layout (unchanged, 55 us).
// ---------------------------------------------------------------------------
static constexpr int HALO = 324;           // 18*18
static constexpr int HPAD = 36;
static constexpr int ATT_SMEM = HALO * HPAD * 4;   // 46656 B

__device__ __forceinline__ void load_halo(float* smf, const float* __restrict__ src,
                                          int ty0, int tx0, int tid) {
    for (int i = tid; i < HALO * 8; i += 256) {
        int pos = i >> 3, f4 = i & 7;
        int yy = pos / 18;
        int xx = pos - yy * 18;
        int gy = ty0 - 1 + yy;
        int gx = tx0 - 1 + xx;
        float4 v = make_float4(0.f, 0.f, 0.f, 0.f);
        if (gy >= 0 && gy < HH && gx >= 0 && gx < WW)
            v = *reinterpret_cast<const float4*>(src + ((size_t)(gy * WW + gx)) * 32 + f4 * 4);
        *reinterpret_cast<float4*>(smf + pos * HPAD + f4 * 4) = v;
    }
}

__global__ __launch_bounds__(256, 4) void attn_kernel(float* __restrict__ out) {
    extern __shared__ char smc[];
    float* smf = reinterpret_cast<float*>(smc);
    const int tid  = threadIdx.x;
    const int tile = blockIdx.x;
    const int ty0  = (tile / 6) * 16;
    const int tx0  = (tile % 6) * 16;
    const int g    = blockIdx.y;
    const int b    = blockIdx.z;
    const int tx = tid & 15;
    const int ty = tid >> 4;

    const size_t hb = (size_t)(b * 4 + g) * 3;
    const float* qb = g_t + (hb + 0) * PP * 32;
    const float* kb = g_t + (hb + 1) * PP * 32;
    const float* vb = g_t + (hb + 2) * PP * 32;

    load_halo(smf, kb, ty0, tx0, tid);

    const float* qp = qb + ((size_t)((ty0 + ty) * WW + tx0 + tx)) * 32;
    float4 q4[8];
#pragma unroll
    for (int j = 0; j < 8; j++) q4[j] = *reinterpret_cast<const float4*>(qp + 4 * j);

    int hp9[9];
#pragma unroll
    for (int n = 0; n < 9; n++) hp9[n] = (ty + n / 3) * 18 + tx + (n % 3);

    __syncthreads();

    float att[9];
#pragma unroll
    for (int n = 0; n < 9; n++) {
        const float* kp = smf + hp9[n] * HPAD;
        float s = 0.f;
#pragma unroll
        for (int j = 0; j < 8; j++) {
            float4 kv = *reinterpret_cast<const float4*>(kp + 4 * j);
            s += q4[j].x * kv.x + q4[j].y * kv.y + q4[j].z * kv.z + q4[j].w * kv.w;
        }
        att[n] = s * RSQRT_D;
    }

    float m = att[0];
#pragma unroll
    for (int n = 1; n < 9; n++) m = fmaxf(m, att[n]);
    float ssum = 0.f;
#pragma unroll
    for (int n = 0; n < 9; n++) { att[n] = __expf(att[n] - m); ssum += att[n]; }
    float inv = 1.f / ssum;
#pragma unroll
    for (int n = 0; n < 9; n++) att[n] *= inv;

    __syncthreads();                 // everyone done reading K
    load_halo(smf, vb, ty0, tx0, tid);
    __syncthreads();

    float* op = out + ((size_t)(b * CIN + g * 32)) * PP + (ty0 + ty) * WW + tx0 + tx;
#pragma unroll
    for (int j = 0; j < 8; j++) {
        float4 acc = make_float4(0.f, 0.f, 0.f, 0.f);
#pragma unroll
        for (int n = 0; n < 9; n++) {
            float4 vv = *reinterpret_cast<const float4*>(smf + hp9[n] * HPAD + 4 * j);
            acc.x += att[n] * vv.x; acc.y += att[n] * vv.y;
            acc.z += att[n] * vv.z; acc.w += att[n] * vv.w;
        }
        op[(size_t)(4 * j + 0) * PP] = acc.x;
        op[(size_t)(4 * j + 1) * PP] = acc.y;
        op[(size_t)(4 * j + 2) * PP] = acc.z;
        op[(size_t)(4 * j + 3) * PP] = acc.w;
    }
}

// ---------------------------------------------------------------------------
extern "C" void kernel_launch(void* const* d_in, const int* in_sizes, int n_in,
                              void* d_out, int out_size) {
    const float* x  = (const float*)d_in[0];   // [8,128,96,96]
    const float* Wt = (const float*)d_in[1];   // [384,128]
    float* out = (float*)d_out;                // [8,128,96,96]

    cudaFuncSetAttribute(qkv_mma,    cudaFuncAttributeMaxDynamicSharedMemorySize, GEMM_SMEM);
    cudaFuncSetAttribute(attn_kernel, cudaFuncAttributeMaxDynamicSharedMemorySize, ATT_SMEM);

    wprep_kernel<<<(384 * 64 + 255) / 256, 256>>>(Wt);
    qkv_mma<<<dim3(PP / 128, BATCH), 256, GEMM_SMEM>>>(x);
    attn_kernel<<<dim3((HH / 16) * (WW / 16), 4, BATCH), 256, ATT_SMEM>>>(out);
}

// round 9
// speedup vs baseline: 3.7851x; 1.1028x over previous
#include <cuda_runtime.h>
#include <cuda_bf16.h>
#include <cstdint>
#include <math.h>

// ---------------------------------------------------------------------------
// Problem constants
// ---------------------------------------------------------------------------
#define BATCH 8
#define CIN   128
#define HH    96
#define WW    96
#define PP    (HH*WW)          // 9216
#define RSQRT_D 0.17677669529663687f

// t layout: [b][g][qkv][p][d]  (d=32 contiguous per position)
__device__ float g_t[(size_t)BATCH * 384 * PP];

// Pre-split W in smem-image layout: [slab(6)][hi/lo(2)][64 rows x 136 bf16]
__device__ __nv_bfloat16 g_wslab[6][2][64 * 136];

// ---------------------------------------------------------------------------
// GEMM smem layout (single W buffer -> 102 KB -> 2 CTAs/SM)
// ---------------------------------------------------------------------------
static constexpr int TS   = 136;        // bf16 elems per row
static constexpr int TSB  = TS * 2;     // 272 bytes
static constexpr int XHI  = 0;                  // 34816 B
static constexpr int XLO  = 128 * TSB;          // 34816
static constexpr int WBUF = 2 * 128 * TSB;      // 69632 (hi 17408 | lo 17408)
static constexpr int WLO_OFF = 64 * TSB;        // 17408
static constexpr int WSLAB_BYTES = 2 * 64 * TSB;  // 34816
static constexpr int GEMM_SMEM = WBUF + WSLAB_BYTES; // 104448 B

__device__ __forceinline__ uint32_t smem_u32(const void* p) {
    uint32_t a;
    asm("{ .reg .u64 t; cvta.to.shared.u64 t, %1; cvt.u32.u64 %0, t; }" : "=r"(a) : "l"(p));
    return a;
}
__device__ __forceinline__ void ldm_x4(uint32_t r[4], uint32_t a) {
    asm volatile("ldmatrix.sync.aligned.m8n8.x4.shared.b16 {%0,%1,%2,%3}, [%4];"
                 : "=r"(r[0]), "=r"(r[1]), "=r"(r[2]), "=r"(r[3]) : "r"(a));
}
__device__ __forceinline__ void mma16816(float* c, const uint32_t* a, const uint32_t* b) {
    asm volatile("mma.sync.aligned.m16n8k16.row.col.f32.bf16.bf16.f32 "
                 "{%0,%1,%2,%3}, {%4,%5,%6,%7}, {%8,%9}, {%0,%1,%2,%3};"
                 : "+f"(c[0]), "+f"(c[1]), "+f"(c[2]), "+f"(c[3])
                 : "r"(a[0]), "r"(a[1]), "r"(a[2]), "r"(a[3]), "r"(b[0]), "r"(b[1]));
}
__device__ __forceinline__ void cp16(uint32_t dst, const void* src) {
    asm volatile("cp.async.ca.shared.global [%0], [%1], 16;" :: "r"(dst), "l"(src));
}
// cp.async with src-size predication: sz=0 -> zero-fill (src not read)
__device__ __forceinline__ void cp16z(uint32_t dst, const void* src, bool ok) {
    int sz = ok ? 16 : 0;
    asm volatile("cp.async.ca.shared.global [%0], [%1], 16, %2;"
                 :: "r"(dst), "l"(src), "r"(sz));
}
__device__ __forceinline__ void cp_commit() {
    asm volatile("cp.async.commit_group;" ::: "memory");
}
__device__ __forceinline__ void cp_wait0() {
    asm volatile("cp.async.wait_group 0;" ::: "memory");
}
// split two fp32 into packed bf16x2 hi + lo (lo = residual)
__device__ __forceinline__ void split2(float f0, float f1, uint32_t& hi, uint32_t& lo) {
    __nv_bfloat16 h0 = __float2bfloat16(f0);
    __nv_bfloat16 h1 = __float2bfloat16(f1);
    __nv_bfloat16 l0 = __float2bfloat16(f0 - __bfloat162float(h0));
    __nv_bfloat16 l1 = __float2bfloat16(f1 - __bfloat162float(h1));
    hi = ((uint32_t)*reinterpret_cast<uint16_t*>(&h1) << 16) | *reinterpret_cast<uint16_t*>(&h0);
    lo = ((uint32_t)*reinterpret_cast<uint16_t*>(&l1) << 16) | *reinterpret_cast<uint16_t*>(&l0);
}

// ---------------------------------------------------------------------------
// Kernel 0: pre-split W into smem-image layout
// ---------------------------------------------------------------------------
__global__ void wprep_kernel(const float* __restrict__ Wt) {
    int i = blockIdx.x * 256 + threadIdx.x;      // over 384*64 channel-pairs
    if (i < 384 * 64) {
        int o = i >> 6, cp = i & 63;
        float2 w = *reinterpret_cast<const float2*>(&Wt[o * 128 + 2 * cp]);
        uint32_t hi, lo;
        split2(w.x, w.y, hi, lo);
        int slab = o >> 6, row = o & 63;
        reinterpret_cast<uint32_t*>(g_wslab[slab][0])[row * 68 + cp] = hi;
        reinterpret_cast<uint32_t*>(g_wslab[slab][1])[row * 68 + cp] = lo;
    }
}

// ---------------------------------------------------------------------------
// Kernel A: QKV GEMM via mma.sync bf16 (3-term hi/lo split, fp32 accum).
// Single W buffer, 2 CTAs/SM; W staging serialization hidden by co-resident
// CTA. 8 warps = 4(p) x 2(o); warp tile 32p x 32o. Grid: (72, 8).
// ---------------------------------------------------------------------------
__global__ __launch_bounds__(256, 2) void qkv_mma(const float* __restrict__ x) {
    extern __shared__ char smc[];
    const uint32_t smb = smem_u32(smc);
    const int tid = threadIdx.x;
    const int p0  = blockIdx.x * 128;
    const int b   = blockIdx.y;

    // ---- Prologue: issue cp.async for W slab 0 ----
    {
        const char* src = reinterpret_cast<const char*>(g_wslab[0]);
        for (int i = tid; i < WSLAB_BYTES / 16; i += 256)
            cp16(smb + WBUF + i * 16, src + i * 16);
        cp_commit();
    }

    // ---- Stage X^T (hi/lo): thread handles half a p-row (64 channels) ----
    {
        const int row  = tid & 127;
        const int half = tid >> 7;
        const float* xp = x + (size_t)b * CIN * PP + p0 + row;
        uint32_t* xh = reinterpret_cast<uint32_t*>(smc + XHI + row * TSB + half * 128);
        uint32_t* xl = reinterpret_cast<uint32_t*>(smc + XLO + row * TSB + half * 128);
#pragma unroll
        for (int j = 0; j < 32; j++) {
            int c = half * 64 + 2 * j;
            float f0 = xp[(size_t)c * PP];
            float f1 = xp[(size_t)(c + 1) * PP];
            uint32_t hi, lo;
            split2(f0, f1, hi, lo);
            xh[j] = hi;
            xl[j] = lo;
        }
    }

    const int lane = tid & 31, wid = tid >> 5;
    const int wp = wid & 3;          // p: 4 x 32
    const int wo = wid >> 2;         // o: 2 x 32
    const int sel = lane >> 3, idx = lane & 7;
    const int gid = lane >> 2, tig = lane & 3;

    const uint32_t aoff = (uint32_t)((idx + (sel & 1) * 8) * TSB + (sel >> 1) * 16);
    const uint32_t boff = (uint32_t)((idx + (sel >> 1) * 8) * TSB + (sel & 1) * 16);
    const uint32_t aHi = smb + XHI + wp * 32 * TSB + aoff;
    const uint32_t aLo = smb + XLO + wp * 32 * TSB + aoff;
    const uint32_t bHi = smb + WBUF + wo * 32 * TSB + boff;
    const uint32_t bLo = bHi + WLO_OFF;

    for (int s = 0; s < 6; s++) {
        cp_wait0();
        __syncthreads();             // W slab visible to all warps (& X on s=0)

        float C[2][4][4];
#pragma unroll
        for (int mf = 0; mf < 2; mf++)
#pragma unroll
            for (int nf = 0; nf < 4; nf++)
#pragma unroll
                for (int r = 0; r < 4; r++) C[mf][nf][r] = 0.f;

#pragma unroll
        for (int ks = 0; ks < 8; ks++) {
            const uint32_t ko = ks * 32;
            uint32_t Ah[2][4], Al[2][4], Bh[2][4], Bl[2][4];
#pragma unroll
            for (int mf = 0; mf < 2; mf++) {
                ldm_x4(Ah[mf], aHi + mf * 16 * TSB + ko);
                ldm_x4(Al[mf], aLo + mf * 16 * TSB + ko);
            }
#pragma unroll
            for (int np = 0; np < 2; np++) {
                ldm_x4(Bh[np], bHi + np * 16 * TSB + ko);
                ldm_x4(Bl[np], bLo + np * 16 * TSB + ko);
            }
#pragma unroll
            for (int mf = 0; mf < 2; mf++) {
#pragma unroll
                for (int nf = 0; nf < 4; nf++) {
                    const uint32_t* bh = &Bh[nf >> 1][(nf & 1) * 2];
                    const uint32_t* bl = &Bl[nf >> 1][(nf & 1) * 2];
                    mma16816(C[mf][nf], Ah[mf], bh);   // hh
                    mma16816(C[mf][nf], Ah[mf], bl);   // hl
                    mma16816(C[mf][nf], Al[mf], bh);   // lh
                }
            }
        }

        __syncthreads();             // all warps done reading WBUF
        if (s < 5) {                 // stream next slab while epilogue runs
            const char* src = reinterpret_cast<const char*>(g_wslab[s + 1]);
            for (int i = tid; i < WSLAB_BYTES / 16; i += 256)
                cp16(smb + WBUF + i * 16, src + i * 16);
            cp_commit();
        }

        // ---- Epilogue: t[b][g][ot][p][d], d-contiguous float2 stores ----
        const int ot = s >> 1;
#pragma unroll
        for (int mf = 0; mf < 2; mf++) {
#pragma unroll
            for (int nf = 0; nf < 4; nf++) {
                const int p_l = wp * 32 + mf * 16 + gid;
                const int oo  = (s & 1) * 64 + wo * 32 + nf * 8 + tig * 2;
                const int g   = oo >> 5;
                const int d   = oo & 31;
                float* dst = g_t + (((size_t)(b * 4 + g) * 3 + ot) * PP + p0 + p_l) * 32 + d;
                *reinterpret_cast<float2*>(dst) = make_float2(C[mf][nf][0], C[mf][nf][1]);
                *reinterpret_cast<float2*>(dst + 8 * 32) = make_float2(C[mf][nf][2], C[mf][nf][3]);
            }
        }
    }
}

// ---------------------------------------------------------------------------
// Kernel B: 3x3 neighborhood attention, halo via cp.async (zero-fill OOB).
// CTA = 16x16 tile, 256 threads; one 18x18x36f halo buffer reused K then V.
// ---------------------------------------------------------------------------
static constexpr int HALO = 324;           // 18*18
static constexpr int HPAD = 36;
static constexpr int ATT_SMEM = HALO * HPAD * 4;   // 46656 B

__device__ __forceinline__ void load_halo_async(uint32_t smb, const float* __restrict__ src,
                                                int ty0, int tx0, int tid) {
    for (int i = tid; i < HALO * 8; i += 256) {
        int pos = i >> 3, c = i & 7;
        int yy = pos / 18;
        int xx = pos - yy * 18;
        int gy = ty0 - 1 + yy;
        int gx = tx0 - 1 + xx;
        bool ok = (gy >= 0) && (gy < HH) && (gx >= 0) && (gx < WW);
        int cgy = ok ? gy : 0, cgx = ok ? gx : 0;    // clamped (unused if !ok)
        const float* sp = src + ((size_t)(cgy * WW + cgx)) * 32 + c * 4;
        cp16z(smb + (uint32_t)(pos * HPAD + c * 4) * 4, sp, ok);
    }
    cp_commit();
}

__global__ __launch_bounds__(256, 4) void attn_kernel(float* __restrict__ out) {
    extern __shared__ char smc[];
    float* smf = reinterpret_cast<float*>(smc);
    const uint32_t smb = smem_u32(smc);
    const int tid  = threadIdx.x;
    const int tile = blockIdx.x;
    const int ty0  = (tile / 6) * 16;
    const int tx0  = (tile % 6) * 16;
    const int g    = blockIdx.y;
    const int b    = blockIdx.z;
    const int tx = tid & 15;
    const int ty = tid >> 4;

    const size_t hb = (size_t)(b * 4 + g) * 3;
    const float* qb = g_t + (hb + 0) * PP * 32;
    const float* kb = g_t + (hb + 1) * PP * 32;
    const float* vb = g_t + (hb + 2) * PP * 32;

    load_halo_async(smb, kb, ty0, tx0, tid);     // K halo in flight

    // q loads overlap with the K-halo cp.async
    const float* qp = qb + ((size_t)((ty0 + ty) * WW + tx0 + tx)) * 32;
    float4 q4[8];
#pragma unroll
    for (int j = 0; j < 8; j++) q4[j] = *reinterpret_cast<const float4*>(qp + 4 * j);

    int hp9[9];
#pragma unroll
    for (int n = 0; n < 9; n++) hp9[n] = (ty + n / 3) * 18 + tx + (n % 3);

    cp_wait0();
    __syncthreads();

    float att[9];
#pragma unroll
    for (int n = 0; n < 9; n++) {
        const float* kp = smf + hp9[n] * HPAD;
        float s = 0.f;
#pragma unroll
        for (int j = 0; j < 8; j++) {
            float4 kv = *reinterpret_cast<const float4*>(kp + 4 * j);
            s += q4[j].x * kv.x + q4[j].y * kv.y + q4[j].z * kv.z + q4[j].w * kv.w;
        }
        att[n] = s * RSQRT_D;
    }

    float m = att[0];
#pragma unroll
    for (int n = 1; n < 9; n++) m = fmaxf(m, att[n]);
    float ssum = 0.f;
#pragma unroll
    for (int n = 0; n < 9; n++) { att[n] = __expf(att[n] - m); ssum += att[n]; }
    float inv = 1.f / ssum;
#pragma unroll
    for (int n = 0; n < 9; n++) att[n] *= inv;

    __syncthreads();                 // everyone done reading K
    load_halo_async(smb, vb, ty0, tx0, tid);
    cp_wait0();
    __syncthreads();

    float* op = out + ((size_t)(b * CIN + g * 32)) * PP + (ty0 + ty) * WW + tx0 + tx;
#pragma unroll
    for (int j = 0; j < 8; j++) {
        float4 acc = make_float4(0.f, 0.f, 0.f, 0.f);
#pragma unroll
        for (int n = 0; n < 9; n++) {
            float4 vv = *reinterpret_cast<const float4*>(smf + hp9[n] * HPAD + 4 * j);
            acc.x += att[n] * vv.x; acc.y += att[n] * vv.y;
            acc.z += att[n] * vv.z; acc.w += att[n] * vv.w;
        }
        op[(size_t)(4 * j + 0) * PP] = acc.x;
        op[(size_t)(4 * j + 1) * PP] = acc.y;
        op[(size_t)(4 * j + 2) * PP] = acc.z;
        op[(size_t)(4 * j + 3) * PP] = acc.w;
    }
}

// ---------------------------------------------------------------------------
extern "C" void kernel_launch(void* const* d_in, const int* in_sizes, int n_in,
                              void* d_out, int out_size) {
    const float* x  = (const float*)d_in[0];   // [8,128,96,96]
    const float* Wt = (const float*)d_in[1];   // [384,128]
    float* out = (float*)d_out;                // [8,128,96,96]

    cudaFuncSetAttribute(qkv_mma,    cudaFuncAttributeMaxDynamicSharedMemorySize, GEMM_SMEM);
    cudaFuncSetAttribute(attn_kernel, cudaFuncAttributeMaxDynamicSharedMemorySize, ATT_SMEM);

    wprep_kernel<<<(384 * 64 + 255) / 256, 256>>>(Wt);
    qkv_mma<<<dim3(PP / 128, BATCH), 256, GEMM_SMEM>>>(x);
    attn_kernel<<<dim3((HH / 16) * (WW / 16), 4, BATCH), 256, ATT_SMEM>>>(out);
}